// round 1
// baseline (speedup 1.0000x reference)
#include <cuda_runtime.h>

#define NNODES 100000
#define KNN 6
#define NEDGES (NNODES * KNN)

// Intermediate node features (device globals: no allocation allowed)
__device__ float g_h1[NNODES * 32];
__device__ float g_h2[NNODES * 64];

// One fused PointNetConv layer:
//   for each node i (tile of NB nodes), its K contiguous edges e=i*K+k, j=src[e]:
//     in  = concat(x[j], pos[j]-pos[i])            [CP = CIN+3]
//     hid = relu(in @ Wa + ba)                      [H]
//     out[i] = relu( max_e (hid_e @ Wb + bb) )      [COUT]
template<int CIN, int H, int COUT, int NB, int THREADS>
__global__ void layer_kernel(const float* __restrict__ x,
                             const float* __restrict__ pos,
                             const int*   __restrict__ src,
                             const float* __restrict__ Wa, const float* __restrict__ ba,
                             const float* __restrict__ Wb, const float* __restrict__ bb,
                             float* __restrict__ out)
{
    constexpr int CP = CIN + 3;
    constexpr int NE = NB * KNN;

    extern __shared__ float smem[];
    float* sWa  = smem;                    // CP*H
    float* sWb  = sWa + CP * H;            // H*COUT
    float* sba  = sWb + H * COUT;          // H
    float* sbb  = sba + H;                 // COUT
    float* sx   = sbb + COUT;              // NE*CP
    float* shid = sx + NE * CP;            // NE*H
    int*   sj   = (int*)(shid + NE * H);   // NE

    const int tid = threadIdx.x;

    // Load weights once per (persistent) block
    for (int t = tid; t < CP * H;   t += THREADS) sWa[t] = Wa[t];
    for (int t = tid; t < H * COUT; t += THREADS) sWb[t] = Wb[t];
    for (int t = tid; t < H;        t += THREADS) sba[t] = ba[t];
    for (int t = tid; t < COUT;     t += THREADS) sbb[t] = bb[t];

    const int numTiles = (NNODES + NB - 1) / NB;
    for (int tile = blockIdx.x; tile < numTiles; tile += gridDim.x) {
        const int base = tile * NB;
        __syncthreads();

        // ---- stage 0a: edge source indices + relative positions ----
        for (int e = tid; e < NE; e += THREADS) {
            int i = base + e / KNN;
            int j = 0;
            if (i < NNODES) {
                j = src[i * KNN + (e % KNN)];
                float px = pos[3 * i], py = pos[3 * i + 1], pz = pos[3 * i + 2];
                sx[e * CP + CIN + 0] = pos[3 * j + 0] - px;
                sx[e * CP + CIN + 1] = pos[3 * j + 1] - py;
                sx[e * CP + CIN + 2] = pos[3 * j + 2] - pz;
            } else {
                sx[e * CP + CIN + 0] = 0.f;
                sx[e * CP + CIN + 1] = 0.f;
                sx[e * CP + CIN + 2] = 0.f;
            }
            sj[e] = j;
        }
        __syncthreads();

        // ---- stage 0b: gather x rows for the edge sources ----
        for (int t = tid; t < NE * CIN; t += THREADS) {
            int e = t / CIN, c = t % CIN;
            sx[e * CP + c] = x[(size_t)sj[e] * CIN + c];
        }
        __syncthreads();

        // ---- stage 1: hidden = relu(in @ Wa + ba) ----
        // thread v -> (edge e = v/H, channel h = v%H): sx read is warp-broadcast,
        // sWa read is stride-1 coalesced in h.
        for (int v = tid; v < NE * H; v += THREADS) {
            int e = v / H, h = v % H;
            float acc = sba[h];
            const float* xr = &sx[e * CP];
            #pragma unroll
            for (int c = 0; c < CP; c++)
                acc = fmaf(xr[c], sWa[c * H + h], acc);
            shid[v] = fmaxf(acc, 0.f);
        }
        __syncthreads();

        // ---- stage 2: out = relu(max_e (hid_e @ Wb + bb)) ----
        // thread -> (node n, 4-channel group cg). 24 FMAs per float4 Wb load.
        constexpr int CG = COUT / 4;
        for (int it = tid; it < NB * CG; it += THREADS) {
            int cg = it % CG;
            int n  = it / CG;
            int i  = base + n;
            if (i >= NNODES) continue;

            float4 bbv = *(const float4*)&sbb[cg * 4];
            float a[KNN][4];
            #pragma unroll
            for (int e = 0; e < KNN; e++) {
                a[e][0] = bbv.x; a[e][1] = bbv.y; a[e][2] = bbv.z; a[e][3] = bbv.w;
            }
            const float* hp = &shid[(n * KNN) * H];
            #pragma unroll 4
            for (int h = 0; h < H; h++) {
                float4 w = *(const float4*)&sWb[h * COUT + cg * 4];
                #pragma unroll
                for (int e = 0; e < KNN; e++) {
                    float s = hp[e * H + h];
                    a[e][0] = fmaf(s, w.x, a[e][0]);
                    a[e][1] = fmaf(s, w.y, a[e][1]);
                    a[e][2] = fmaf(s, w.z, a[e][2]);
                    a[e][3] = fmaf(s, w.w, a[e][3]);
                }
            }
            float4 r = make_float4(a[0][0], a[0][1], a[0][2], a[0][3]);
            #pragma unroll
            for (int e = 1; e < KNN; e++) {
                r.x = fmaxf(r.x, a[e][0]);
                r.y = fmaxf(r.y, a[e][1]);
                r.z = fmaxf(r.z, a[e][2]);
                r.w = fmaxf(r.w, a[e][3]);
            }
            r.x = fmaxf(r.x, 0.f); r.y = fmaxf(r.y, 0.f);
            r.z = fmaxf(r.z, 0.f); r.w = fmaxf(r.w, 0.f);
            *(float4*)&out[(size_t)i * COUT + cg * 4] = r;
        }
    }
}

template<int CIN, int H, int COUT, int NB, int THREADS>
static constexpr int smem_bytes() {
    constexpr int CP = CIN + 3;
    constexpr int NE = NB * KNN;
    return (CP * H + H * COUT + H + COUT + NE * CP + NE * H) * 4 + NE * 4;
}

extern "C" void kernel_launch(void* const* d_in, const int* in_sizes, int n_in,
                              void* d_out, int out_size)
{
    const float* pos = (const float*)d_in[0];
    const int*   ei  = (const int*)d_in[1];     // [2, E]; row0 = src
    const float* W1a = (const float*)d_in[2];
    const float* b1a = (const float*)d_in[3];
    const float* W1b = (const float*)d_in[4];
    const float* b1b = (const float*)d_in[5];
    const float* W2a = (const float*)d_in[6];
    const float* b2a = (const float*)d_in[7];
    const float* W2b = (const float*)d_in[8];
    const float* b2b = (const float*)d_in[9];
    const float* W3a = (const float*)d_in[10];
    const float* b3a = (const float*)d_in[11];
    const float* W3b = (const float*)d_in[12];
    const float* b3b = (const float*)d_in[13];
    float* out = (float*)d_out;

    const int* src = ei;   // dst is repeat(arange(N), K) by construction

    float* h1;  cudaGetSymbolAddress((void**)&h1, g_h1);
    float* h2;  cudaGetSymbolAddress((void**)&h2, g_h2);

    constexpr int NB = 16, TH = 256;

    constexpr int S1 = smem_bytes<3,  32,  32, NB, TH>();
    constexpr int S2 = smem_bytes<32, 64,  64, NB, TH>();
    constexpr int S3 = smem_bytes<64, 128, 128, NB, TH>();

    cudaFuncSetAttribute(layer_kernel<3,  32,  32, NB, TH>,
                         cudaFuncAttributeMaxDynamicSharedMemorySize, S1);
    cudaFuncSetAttribute(layer_kernel<32, 64,  64, NB, TH>,
                         cudaFuncAttributeMaxDynamicSharedMemorySize, S2);
    cudaFuncSetAttribute(layer_kernel<64, 128, 128, NB, TH>,
                         cudaFuncAttributeMaxDynamicSharedMemorySize, S3);

    // Persistent grids sized to occupancy (smem-limited)
    layer_kernel<3,  32,  32, NB, TH><<<888, TH, S1>>>(pos, pos, src, W1a, b1a, W1b, b1b, h1);
    layer_kernel<32, 64,  64, NB, TH><<<444, TH, S2>>>(h1,  pos, src, W2a, b2a, W2b, b2b, h2);
    layer_kernel<64, 128, 128, NB, TH><<<148, TH, S3>>>(h2,  pos, src, W3a, b3a, W3b, b3b, out);
}

// round 2
// speedup vs baseline: 1.7252x; 1.7252x over previous
#include <cuda_runtime.h>

#define NNODES 100000
#define KNN 6
#define NEDGES (NNODES * KNN)

// Scratch (device globals: no allocation allowed)
__device__ float g_hid[(size_t)NEDGES * 128];  // per-edge hidden, reused each layer
__device__ float g_h1[(size_t)NNODES * 32];
__device__ float g_h2[(size_t)NNODES * 64];

typedef unsigned long long u64;

__device__ __forceinline__ u64 ffma2(u64 a, u64 b, u64 c) {
    asm("fma.rn.f32x2 %0, %1, %2, %0;" : "+l"(c) : "l"(a), "l"(b));
    return c;
}
__device__ __forceinline__ u64 dup2(float x) {
    u64 r; asm("mov.b64 %0, {%1, %1};" : "=l"(r) : "f"(x)); return r;
}
__device__ __forceinline__ float2 unpack2(u64 v) {
    float2 f; asm("mov.b64 {%0, %1}, %2;" : "=f"(f.x), "=f"(f.y) : "l"(v)); return f;
}

// ---------------- Stage 1: hid[e] = relu(concat(x[src[e]], pos[src]-pos[dst]) @ Wa + ba)
// f32x2 over channel pairs; x duplicated into float2 smem at gather time.
// Thread tile: 2 edges x 8 channels.
template<int CIN, int H, int TH>
__global__ __launch_bounds__(TH) void stage1(const float* __restrict__ x,
                                             const float* __restrict__ pos,
                                             const int*   __restrict__ src,
                                             const float* __restrict__ Wa,
                                             const float* __restrict__ ba,
                                             float* __restrict__ hid)
{
    constexpr int CP    = CIN + 3;
    constexpr int HG    = H / 8;          // channel groups of 8
    constexpr int PAIRS = TH / HG;        // edge pairs per tile
    constexpr int NE_T  = 2 * PAIRS;

    extern __shared__ float smem[];
    float*  sWa = smem;                         // CP*H
    float*  sba = sWa + CP * H;                 // H
    float2* sx2 = (float2*)(sba + H);           // NE_T*CP  (duplicated values)
    int*    sj  = (int*)(sx2 + NE_T * CP);      // NE_T

    const int tid = threadIdx.x;
    for (int t = tid; t < CP * H; t += TH) sWa[t] = Wa[t];
    for (int t = tid; t < H;      t += TH) sba[t] = ba[t];

    const int g = tid % HG;      // channel group
    const int p = tid / HG;      // edge pair
    const int numTiles = (NEDGES + NE_T - 1) / NE_T;

    for (int tile = blockIdx.x; tile < numTiles; tile += gridDim.x) {
        const int base = tile * NE_T;
        __syncthreads();

        // A: src indices + relative positions
        for (int e = tid; e < NE_T; e += TH) {
            int ge = base + e;
            int i = 0, j = 0;
            if (ge < NEDGES) { i = ge / KNN; j = src[ge]; }
            sj[e] = j;
            float d0 = pos[3 * j + 0] - pos[3 * i + 0];
            float d1 = pos[3 * j + 1] - pos[3 * i + 1];
            float d2 = pos[3 * j + 2] - pos[3 * i + 2];
            sx2[e * CP + CIN + 0] = make_float2(d0, d0);
            sx2[e * CP + CIN + 1] = make_float2(d1, d1);
            sx2[e * CP + CIN + 2] = make_float2(d2, d2);
        }
        __syncthreads();

        // B: gather x rows (duplicated)
        if (CIN % 4 == 0) {
            constexpr int Q = (CIN % 4 == 0) ? CIN / 4 : 1;
            for (int t = tid; t < NE_T * Q; t += TH) {
                int e = t / Q, q = t % Q;
                const float4 v = *(const float4*)&x[(size_t)sj[e] * CIN + 4 * q];
                float2* d = &sx2[e * CP + 4 * q];
                d[0] = make_float2(v.x, v.x);
                d[1] = make_float2(v.y, v.y);
                d[2] = make_float2(v.z, v.z);
                d[3] = make_float2(v.w, v.w);
            }
        } else {
            for (int t = tid; t < NE_T * CIN; t += TH) {
                int e = t / CIN, c = t % CIN;
                float v = x[(size_t)sj[e] * CIN + c];
                sx2[e * CP + c] = make_float2(v, v);
            }
        }
        __syncthreads();

        // Compute: 2 edges x 8 channels per thread
        const int e0 = 2 * p, e1 = e0 + 1;
        u64 accA[4], accB[4];
        #pragma unroll
        for (int m = 0; m < 4; m++) {
            u64 b = *(const u64*)&sba[g * 8 + 2 * m];
            accA[m] = b; accB[m] = b;
        }
        const float2* xa = &sx2[e0 * CP];
        const float2* xb = &sx2[e1 * CP];
        #pragma unroll 2
        for (int c = 0; c < CP; c++) {
            u64 va = *(const u64*)&xa[c];
            u64 vb = *(const u64*)&xb[c];
            const u64* wp = (const u64*)&sWa[c * H + g * 8];
            u64 w0 = wp[0], w1 = wp[1], w2 = wp[2], w3 = wp[3];
            accA[0] = ffma2(va, w0, accA[0]);
            accA[1] = ffma2(va, w1, accA[1]);
            accA[2] = ffma2(va, w2, accA[2]);
            accA[3] = ffma2(va, w3, accA[3]);
            accB[0] = ffma2(vb, w0, accB[0]);
            accB[1] = ffma2(vb, w1, accB[1]);
            accB[2] = ffma2(vb, w2, accB[2]);
            accB[3] = ffma2(vb, w3, accB[3]);
        }

        const int ge0 = base + e0, ge1 = base + e1;
        if (ge0 < NEDGES) {
            float2 a0 = unpack2(accA[0]), a1 = unpack2(accA[1]);
            float2 a2 = unpack2(accA[2]), a3 = unpack2(accA[3]);
            float4 r0 = make_float4(fmaxf(a0.x,0.f), fmaxf(a0.y,0.f), fmaxf(a1.x,0.f), fmaxf(a1.y,0.f));
            float4 r1 = make_float4(fmaxf(a2.x,0.f), fmaxf(a2.y,0.f), fmaxf(a3.x,0.f), fmaxf(a3.y,0.f));
            *(float4*)&hid[(size_t)ge0 * H + g * 8]     = r0;
            *(float4*)&hid[(size_t)ge0 * H + g * 8 + 4] = r1;
        }
        if (ge1 < NEDGES) {
            float2 a0 = unpack2(accB[0]), a1 = unpack2(accB[1]);
            float2 a2 = unpack2(accB[2]), a3 = unpack2(accB[3]);
            float4 r0 = make_float4(fmaxf(a0.x,0.f), fmaxf(a0.y,0.f), fmaxf(a1.x,0.f), fmaxf(a1.y,0.f));
            float4 r1 = make_float4(fmaxf(a2.x,0.f), fmaxf(a2.y,0.f), fmaxf(a3.x,0.f), fmaxf(a3.y,0.f));
            *(float4*)&hid[(size_t)ge1 * H + g * 8]     = r0;
            *(float4*)&hid[(size_t)ge1 * H + g * 8 + 4] = r1;
        }
    }
}

// ---------------- Stage 2: out[i] = relu(max_e(hid[e] @ Wb) + bb)
// f32x2 over edge pairs via transposed hid tile shT[h][e] (+2 pad: conflict-free, 8B aligned).
// Thread tile: 1 node x 4 columns (3 edge-pairs accumulated).
template<int H, int COUT, int NB>
__global__ __launch_bounds__(NB*(COUT/4)) void stage2(const float* __restrict__ hid,
                                                      const float* __restrict__ Wb,
                                                      const float* __restrict__ bb,
                                                      float* __restrict__ out)
{
    constexpr int CG    = COUT / 4;
    constexpr int TH    = NB * CG;
    constexpr int NE_T  = NB * KNN;
    constexpr int NE_TP = NE_T + 2;

    extern __shared__ float smem[];
    float* sWb = smem;                 // H*COUT
    float* shT = sWb + H * COUT;       // H*NE_TP (transposed hid tile)

    const int tid = threadIdx.x;
    for (int t = tid; t < H * COUT; t += TH) sWb[t] = Wb[t];

    const int n  = tid / CG;
    const int cg = tid % CG;
    const int c0 = cg * 4;
    const float4 bbv = *(const float4*)&bb[c0];

    const int numTiles = (NNODES + NB - 1) / NB;

    for (int tile = blockIdx.x; tile < numTiles; tile += gridDim.x) {
        const int base = tile * NB;
        __syncthreads();

        // Fill transposed hid tile (coalesced global reads)
        for (int t = tid; t < NE_T * H; t += TH) {
            int e = t / H, h = t % H;
            long long gi = (long long)base * KNN + e;
            float v = (gi < (long long)NEDGES) ? hid[(size_t)gi * H + h] : 0.f;
            shT[h * NE_TP + e] = v;
        }
        __syncthreads();

        u64 acc[3][4];
        #pragma unroll
        for (int q = 0; q < 3; q++)
            #pragma unroll
            for (int j = 0; j < 4; j++) acc[q][j] = 0ull;

        #pragma unroll 4
        for (int h = 0; h < H; h++) {
            const float4 w = *(const float4*)&sWb[h * COUT + c0];
            u64 w0 = dup2(w.x), w1 = dup2(w.y), w2 = dup2(w.z), w3 = dup2(w.w);
            const float* sr = &shT[h * NE_TP + n * KNN];
            #pragma unroll
            for (int q = 0; q < 3; q++) {
                u64 s2 = *(const u64*)&sr[2 * q];
                acc[q][0] = ffma2(s2, w0, acc[q][0]);
                acc[q][1] = ffma2(s2, w1, acc[q][1]);
                acc[q][2] = ffma2(s2, w2, acc[q][2]);
                acc[q][3] = ffma2(s2, w3, acc[q][3]);
            }
        }

        const int i = base + n;
        if (i < NNODES) {
            float m[4];
            #pragma unroll
            for (int j = 0; j < 4; j++) {
                float2 a0 = unpack2(acc[0][j]);
                float2 a1 = unpack2(acc[1][j]);
                float2 a2 = unpack2(acc[2][j]);
                m[j] = fmaxf(fmaxf(fmaxf(a0.x, a0.y), fmaxf(a1.x, a1.y)),
                             fmaxf(a2.x, a2.y));
            }
            float4 r = make_float4(fmaxf(m[0] + bbv.x, 0.f),
                                   fmaxf(m[1] + bbv.y, 0.f),
                                   fmaxf(m[2] + bbv.z, 0.f),
                                   fmaxf(m[3] + bbv.w, 0.f));
            *(float4*)&out[(size_t)i * COUT + c0] = r;
        }
    }
}

extern "C" void kernel_launch(void* const* d_in, const int* in_sizes, int n_in,
                              void* d_out, int out_size)
{
    const float* pos = (const float*)d_in[0];
    const int*   src = (const int*)d_in[1];   // row 0 of edge_index
    const float* W1a = (const float*)d_in[2];
    const float* b1a = (const float*)d_in[3];
    const float* W1b = (const float*)d_in[4];
    const float* b1b = (const float*)d_in[5];
    const float* W2a = (const float*)d_in[6];
    const float* b2a = (const float*)d_in[7];
    const float* W2b = (const float*)d_in[8];
    const float* b2b = (const float*)d_in[9];
    const float* W3a = (const float*)d_in[10];
    const float* b3a = (const float*)d_in[11];
    const float* W3b = (const float*)d_in[12];
    const float* b3b = (const float*)d_in[13];
    float* out = (float*)d_out;

    float* hid; cudaGetSymbolAddress((void**)&hid, g_hid);
    float* h1;  cudaGetSymbolAddress((void**)&h1,  g_h1);
    float* h2;  cudaGetSymbolAddress((void**)&h2,  g_h2);

    // shared-memory sizes
    constexpr int S1_1 = (6*32 + 32) * 4 + 128*6*8 + 128*4;     // stage1<3,32,256>
    constexpr int S1_2 = (35*64 + 64) * 4 + 64*35*8 + 64*4;     // stage1<32,64,256>
    constexpr int S1_3 = (67*128 + 128) * 4 + 32*67*8 + 32*4;   // stage1<64,128,256>
    constexpr int S2_1 = 32*32*4  + 32*(64*6+2)*4;              // stage2<32,32,64>
    constexpr int S2_2 = 64*64*4  + 64*(32*6+2)*4;              // stage2<64,64,32>
    constexpr int S2_3 = 128*128*4 + 128*(12*6+2)*4;            // stage2<128,128,12>

    cudaFuncSetAttribute(stage1<3,32,256>,    cudaFuncAttributeMaxDynamicSharedMemorySize, S1_1);
    cudaFuncSetAttribute(stage1<32,64,256>,   cudaFuncAttributeMaxDynamicSharedMemorySize, S1_2);
    cudaFuncSetAttribute(stage1<64,128,256>,  cudaFuncAttributeMaxDynamicSharedMemorySize, S1_3);
    cudaFuncSetAttribute(stage2<32,32,64>,    cudaFuncAttributeMaxDynamicSharedMemorySize, S2_1);
    cudaFuncSetAttribute(stage2<64,64,32>,    cudaFuncAttributeMaxDynamicSharedMemorySize, S2_2);
    cudaFuncSetAttribute(stage2<128,128,12>,  cudaFuncAttributeMaxDynamicSharedMemorySize, S2_3);

    // Layer 1: pos(3) -> 32
    stage1<3,32,256>   <<<1184, 256, S1_1>>>(pos, pos, src, W1a, b1a, hid);
    stage2<32,32,64>   <<<592,  512, S2_1>>>(hid, W1b, b1b, h1);
    // Layer 2: 32 -> 64
    stage1<32,64,256>  <<<1184, 256, S1_2>>>(h1, pos, src, W2a, b2a, hid);
    stage2<64,64,32>   <<<444,  512, S2_2>>>(hid, W2b, b2b, h2);
    // Layer 3: 64 -> 128
    stage1<64,128,256> <<<592,  256, S1_3>>>(h2, pos, src, W3a, b3a, hid);
    stage2<128,128,12> <<<296,  384, S2_3>>>(hid, W3b, b3b, out);
}

// round 4
// speedup vs baseline: 3.4396x; 1.9937x over previous
#include <cuda_runtime.h>
#include <cuda_bf16.h>
#include <stdint.h>

#define NNODES 100000
#define KNN 6
#define NEDGES 600000

// ---------------- device scratch (no allocation allowed) ----------------
__device__ __nv_bfloat16 g_hA[(size_t)NEDGES * 128];   // hid hi (bf16), row stride = KDIM
__device__ __nv_bfloat16 g_lA[(size_t)NEDGES * 128];   // hid lo (bf16)
__device__ float g_y [(size_t)NNODES * 128];           // node-level partial (x@Wa_top + ba)
__device__ float g_h1[(size_t)NNODES * 32];
__device__ float g_h2[(size_t)NNODES * 64];
__device__ __nv_bfloat16 g_WTh[128 * 128];             // Wb^T hi  [COUT][KDIM]
__device__ __nv_bfloat16 g_WTl[128 * 128];             // Wb^T lo

// ---------------- PTX helpers (sm_80+ only: mma.sync / ldmatrix) ----------------
__device__ __forceinline__ uint32_t s2u(const void* p) {
    uint32_t a;
    asm("{ .reg .u64 t; cvta.to.shared.u64 t, %1; cvt.u32.u64 %0, t; }" : "=r"(a) : "l"(p));
    return a;
}
__device__ __forceinline__ void ldm_x4(uint32_t* r, uint32_t addr) {
    asm volatile("ldmatrix.sync.aligned.m8n8.x4.shared.b16 {%0,%1,%2,%3}, [%4];"
                 : "=r"(r[0]), "=r"(r[1]), "=r"(r[2]), "=r"(r[3]) : "r"(addr));
}
__device__ __forceinline__ void mma_bf16(float* c, const uint32_t* a, const uint32_t* b) {
    asm volatile("mma.sync.aligned.m16n8k16.row.col.f32.bf16.bf16.f32 "
                 "{%0,%1,%2,%3}, {%4,%5,%6,%7}, {%8,%9}, {%0,%1,%2,%3};"
                 : "+f"(c[0]), "+f"(c[1]), "+f"(c[2]), "+f"(c[3])
                 : "r"(a[0]), "r"(a[1]), "r"(a[2]), "r"(a[3]), "r"(b[0]), "r"(b[1]));
}

// ============ kernelN: y[node] = x @ Wa_top + ba  (warp per node) ============
template<int CIN, int H>
__global__ __launch_bounds__(256) void kernelN(const float* __restrict__ x,
                                               const float* __restrict__ Wa,
                                               const float* __restrict__ ba,
                                               float* __restrict__ y)
{
    constexpr int CPL = H / 32;
    __shared__ float sW[CIN * H];
    __shared__ float sb[H];
    for (int t = threadIdx.x; t < CIN * H; t += 256) sW[t] = Wa[t];
    for (int t = threadIdx.x; t < H;       t += 256) sb[t] = ba[t];
    __syncthreads();

    const int lane = threadIdx.x & 31;
    const int gw = (blockIdx.x * 256 + threadIdx.x) >> 5;
    const int nw = (gridDim.x * 256) >> 5;
    const int c0 = lane * CPL;

    for (int node = gw; node < NNODES; node += nw) {
        float acc[CPL];
        #pragma unroll
        for (int q = 0; q < CPL; q++) acc[q] = sb[c0 + q];
        #pragma unroll 4
        for (int c = 0; c < CIN; c++) {
            float xv = __ldg(&x[(size_t)node * CIN + c]);
            #pragma unroll
            for (int q = 0; q < CPL; q++) acc[q] = fmaf(xv, sW[c * H + c0 + q], acc[q]);
        }
        #pragma unroll
        for (int q = 0; q < CPL; q++) y[(size_t)node * H + c0 + q] = acc[q];
    }
}

// ============ kernelE: hid[e] = relu(y[src[e]] + dpos @ Wa_pos) -> bf16 hi/lo ============
template<int CIN, int H, int KDIM>
__global__ __launch_bounds__(256) void kernelE(const float* __restrict__ y,
                                               const float* __restrict__ pos,
                                               const int*   __restrict__ src,
                                               const float* __restrict__ Wa,   // full [CIN+3][H]
                                               __nv_bfloat16* __restrict__ hA,
                                               __nv_bfloat16* __restrict__ lA)
{
    constexpr int CPL = KDIM / 32;
    const int lane = threadIdx.x & 31;
    const int gw = (blockIdx.x * 256 + threadIdx.x) >> 5;
    const int nw = (gridDim.x * 256) >> 5;
    const float* Wp = Wa + CIN * H;   // 3 x H

    for (int e = gw; e < NEDGES; e += nw) {
        const int i = e / KNN;
        const int j = __ldg(&src[e]);
        const float d0 = __ldg(&pos[3 * j + 0]) - __ldg(&pos[3 * i + 0]);
        const float d1 = __ldg(&pos[3 * j + 1]) - __ldg(&pos[3 * i + 1]);
        const float d2 = __ldg(&pos[3 * j + 2]) - __ldg(&pos[3 * i + 2]);

        const int c0 = lane * CPL;
        __align__(8) __nv_bfloat16 hv[CPL], lv[CPL];
        #pragma unroll
        for (int q = 0; q < CPL; q++) {
            const int c = c0 + q;
            float v = 0.f;
            if (c < H) {
                v = __ldg(&y[(size_t)j * H + c]);
                v = fmaf(d0, __ldg(&Wp[0 * H + c]), v);
                v = fmaf(d1, __ldg(&Wp[1 * H + c]), v);
                v = fmaf(d2, __ldg(&Wp[2 * H + c]), v);
                v = fmaxf(v, 0.f);
            }
            __nv_bfloat16 h = __float2bfloat16(v);
            hv[q] = h;
            lv[q] = __float2bfloat16(v - __bfloat162float(h));
        }
        if (CPL == 2) {
            *(uint32_t*)&hA[(size_t)e * KDIM + c0] = *(uint32_t*)hv;
            *(uint32_t*)&lA[(size_t)e * KDIM + c0] = *(uint32_t*)lv;
        } else {
            *(uint2*)&hA[(size_t)e * KDIM + c0] = *(uint2*)hv;
            *(uint2*)&lA[(size_t)e * KDIM + c0] = *(uint2*)lv;
        }
    }
}

// ============ prepT: Wb [H][COUT] -> WbT hi/lo [COUT][KDIM] (zero-pad k>=H) ============
template<int H, int COUT, int KDIM>
__global__ __launch_bounds__(256) void prepT(const float* __restrict__ Wb,
                                             __nv_bfloat16* __restrict__ WTh,
                                             __nv_bfloat16* __restrict__ WTl)
{
    for (int t = blockIdx.x * 256 + threadIdx.x; t < COUT * KDIM; t += gridDim.x * 256) {
        int n = t / KDIM, k = t % KDIM;
        float v = (k < H) ? Wb[k * COUT + n] : 0.f;
        __nv_bfloat16 h = __float2bfloat16(v);
        WTh[t] = h;
        WTl[t] = __float2bfloat16(v - __bfloat162float(h));
    }
}

// ============ stage2m: z = hid @ WbT^T via mma.sync bf16 split, then 6-row max ============
// M-tile = 256 rows = 252 edges (42 nodes) + 4 dead rows. 512 threads = 16 warps,
// warp w owns rows [16w, 16w+16). B (weights hi/lo) resident in smem across tiles.
// z output tile aliases the A region (guarded by __syncthreads).
template<int KDIM, int N>
__global__ __launch_bounds__(512) void stage2m(const __nv_bfloat16* __restrict__ hA,
                                               const __nv_bfloat16* __restrict__ lA,
                                               const __nv_bfloat16* __restrict__ WTh,
                                               const __nv_bfloat16* __restrict__ WTl,
                                               const float* __restrict__ bb,
                                               float* __restrict__ out)
{
    constexpr int M    = 256;
    constexpr int SA   = KDIM + 8;          // padded row stride (bf16 elements)
    constexpr int NP   = N + 4;             // padded z row (floats)
    constexpr int NT8  = N / 8;             // n-tiles of 8 cols
    constexpr int OFF_AH = 0;
    constexpr int OFF_AL = M * SA * 2;
    constexpr int OFF_BH = 2 * M * SA * 2;
    constexpr int OFF_BL = OFF_BH + N * SA * 2;

    extern __shared__ char smem[];
    const uint32_t sb = s2u(smem);
    float* z = (float*)smem;                 // aliases A region (NP <= SA guarantees fit)

    const int tid  = threadIdx.x;
    const int wid  = tid >> 5;
    const int lid  = tid & 31;
    const int wrow = wid * 16;

    // ---- load weight tiles (hi/lo) once ----
    {
        constexpr int CPR = KDIM / 8;        // uint4 chunks per row
        for (int t = tid; t < N * CPR; t += 512) {
            int r = t / CPR, ck = t % CPR;
            *(uint4*)(smem + OFF_BH + (r * SA + ck * 8) * 2) = *(const uint4*)(WTh + (size_t)r * KDIM + ck * 8);
            *(uint4*)(smem + OFF_BL + (r * SA + ck * 8) * 2) = *(const uint4*)(WTl + (size_t)r * KDIM + ck * 8);
        }
    }

    // ldmatrix lane addressing
    const int lm = lid >> 3, lr = lid & 7;
    const int a_row_off = (lm & 1) * 8 + lr;         // + k-block (lm>>1)*8
    const int b_row_off = (lm >> 1) * 8 + lr;        // + k-block (lm&1)*8

    const int NT = (NEDGES + 251) / 252;

    for (int tile = blockIdx.x; tile < NT; tile += gridDim.x) {
        const int ebase = tile * 252;
        __syncthreads();   // prev tile's z fully consumed before overwriting A region

        // ---- load A tile hi/lo (coalesced, clamp OOB rows to row 0) ----
        {
            constexpr int CPR = KDIM / 8;
            for (int t = tid; t < M * CPR; t += 512) {
                int r = t / CPR, ck = t % CPR;
                int row = ebase + r;
                if (row >= NEDGES) row = 0;
                *(uint4*)(smem + OFF_AH + (r * SA + ck * 8) * 2) = *(const uint4*)(hA + (size_t)row * KDIM + ck * 8);
                *(uint4*)(smem + OFF_AL + (r * SA + ck * 8) * 2) = *(const uint4*)(lA + (size_t)row * KDIM + ck * 8);
            }
        }
        __syncthreads();

        // ---- MMA mainloop: C = Ah*Bh + Ah*Bl + Al*Bh ----
        float c[NT8][4];
        #pragma unroll
        for (int t = 0; t < NT8; t++)
            #pragma unroll
            for (int q = 0; q < 4; q++) c[t][q] = 0.f;

        #pragma unroll
        for (int k0 = 0; k0 < KDIM; k0 += 16) {
            uint32_t ah[4], al[4];
            const uint32_t a_off = ((wrow + a_row_off) * SA + k0 + (lm >> 1) * 8) * 2;
            ldm_x4(ah, sb + OFF_AH + a_off);
            ldm_x4(al, sb + OFF_AL + a_off);

            #pragma unroll
            for (int np = 0; np < NT8 / 2; np++) {
                uint32_t bh[4], bl[4];
                const uint32_t b_off = ((np * 16 + b_row_off) * SA + k0 + (lm & 1) * 8) * 2;
                ldm_x4(bh, sb + OFF_BH + b_off);
                ldm_x4(bl, sb + OFF_BL + b_off);
                mma_bf16(c[2 * np],     ah, bh);
                mma_bf16(c[2 * np],     ah, bh + 2 - 2);   // placeholder removed below
                // (see corrected sequence)
                mma_bf16(c[2 * np + 1], ah, bh + 2);
            }
        }
        // NOTE: the loop above is replaced by the correct full sequence below.
        // (kept structure minimal — see stage2m_real)
        (void)c;
        break;
    }
}

// ---- The real stage2m (clean version) ----
template<int KDIM, int N>
__global__ __launch_bounds__(512) void stage2r(const __nv_bfloat16* __restrict__ hA,
                                               const __nv_bfloat16* __restrict__ lA,
                                               const __nv_bfloat16* __restrict__ WTh,
                                               const __nv_bfloat16* __restrict__ WTl,
                                               const float* __restrict__ bb,
                                               float* __restrict__ out)
{
    constexpr int M    = 256;
    constexpr int SA   = KDIM + 8;
    constexpr int NP   = N + 4;
    constexpr int NT8  = N / 8;
    constexpr int OFF_AH = 0;
    constexpr int OFF_AL = M * SA * 2;
    constexpr int OFF_BH = 2 * M * SA * 2;
    constexpr int OFF_BL = OFF_BH + N * SA * 2;

    extern __shared__ char smem[];
    const uint32_t sb = s2u(smem);
    float* z = (float*)smem;

    const int tid  = threadIdx.x;
    const int wid  = tid >> 5;
    const int lid  = tid & 31;
    const int wrow = wid * 16;

    {
        constexpr int CPR = KDIM / 8;
        for (int t = tid; t < N * CPR; t += 512) {
            int r = t / CPR, ck = t % CPR;
            *(uint4*)(smem + OFF_BH + (r * SA + ck * 8) * 2) = *(const uint4*)(WTh + (size_t)r * KDIM + ck * 8);
            *(uint4*)(smem + OFF_BL + (r * SA + ck * 8) * 2) = *(const uint4*)(WTl + (size_t)r * KDIM + ck * 8);
        }
    }

    const int lm = lid >> 3, lr = lid & 7;
    const int a_row_off = (lm & 1) * 8 + lr;
    const int b_row_off = (lm >> 1) * 8 + lr;
    const int NT = (NEDGES + 251) / 252;

    for (int tile = blockIdx.x; tile < NT; tile += gridDim.x) {
        const int ebase = tile * 252;
        __syncthreads();

        {
            constexpr int CPR = KDIM / 8;
            for (int t = tid; t < M * CPR; t += 512) {
                int r = t / CPR, ck = t % CPR;
                int row = ebase + r;
                if (row >= NEDGES) row = 0;
                *(uint4*)(smem + OFF_AH + (r * SA + ck * 8) * 2) = *(const uint4*)(hA + (size_t)row * KDIM + ck * 8);
                *(uint4*)(smem + OFF_AL + (r * SA + ck * 8) * 2) = *(const uint4*)(lA + (size_t)row * KDIM + ck * 8);
            }
        }
        __syncthreads();

        float c[NT8][4];
        #pragma unroll
        for (int t = 0; t < NT8; t++)
            #pragma unroll
            for (int q = 0; q < 4; q++) c[t][q] = 0.f;

        #pragma unroll
        for (int k0 = 0; k0 < KDIM; k0 += 16) {
            uint32_t ah[4], al[4];
            const uint32_t a_off = ((wrow + a_row_off) * SA + k0 + (lm >> 1) * 8) * 2;
            ldm_x4(ah, sb + OFF_AH + a_off);
            ldm_x4(al, sb + OFF_AL + a_off);

            #pragma unroll
            for (int np = 0; np < NT8 / 2; np++) {
                uint32_t bh[4], bl[4];
                const uint32_t b_off = ((np * 16 + b_row_off) * SA + k0 + (lm & 1) * 8) * 2;
                ldm_x4(bh, sb + OFF_BH + b_off);
                ldm_x4(bl, sb + OFF_BL + b_off);
                // n-tile 2*np: B frag = {bh[0],bh[1]} ; n-tile 2*np+1: {bh[2],bh[3]}
                mma_bf16(c[2 * np],     ah, &bh[0]);
                mma_bf16(c[2 * np],     ah, &bl[0]);
                mma_bf16(c[2 * np],     al, &bh[0]);
                mma_bf16(c[2 * np + 1], ah, &bh[2]);
                mma_bf16(c[2 * np + 1], ah, &bl[2]);
                mma_bf16(c[2 * np + 1], al, &bh[2]);
            }
        }
        __syncthreads();   // all warps done reading A before z overwrites it

        // ---- store C frags to z (rows wrow..wrow+15) ----
        {
            const int qr = lid >> 2, qc = (lid & 3) * 2;
            #pragma unroll
            for (int t = 0; t < NT8; t++) {
                float* zp = z + (wrow + qr) * NP + t * 8 + qc;
                zp[0] = c[t][0];
                zp[1] = c[t][1];
                zp[8 * NP] = c[t][2];
                zp[8 * NP + 1] = c[t][3];
            }
        }
        __syncthreads();

        // ---- 6-row max + bias + relu -> out (42 nodes per tile) ----
        for (int t = tid; t < 42 * N; t += 512) {
            int g = t / N, ccol = t % N;
            int node = tile * 42 + g;
            if (node < NNODES) {
                const float* zp = z + (6 * g) * NP + ccol;
                float m = zp[0];
                m = fmaxf(m, zp[NP]);
                m = fmaxf(m, zp[2 * NP]);
                m = fmaxf(m, zp[3 * NP]);
                m = fmaxf(m, zp[4 * NP]);
                m = fmaxf(m, zp[5 * NP]);
                out[(size_t)node * N + ccol] = fmaxf(m + __ldg(&bb[ccol]), 0.f);
            }
        }
    }
}

// ---------------- host ----------------
extern "C" void kernel_launch(void* const* d_in, const int* in_sizes, int n_in,
                              void* d_out, int out_size)
{
    const float* pos = (const float*)d_in[0];
    const int*   src = (const int*)d_in[1];   // row 0 of edge_index
    const float* W1a = (const float*)d_in[2];
    const float* b1a = (const float*)d_in[3];
    const float* W1b = (const float*)d_in[4];
    const float* b1b = (const float*)d_in[5];
    const float* W2a = (const float*)d_in[6];
    const float* b2a = (const float*)d_in[7];
    const float* W2b = (const float*)d_in[8];
    const float* b2b = (const float*)d_in[9];
    const float* W3a = (const float*)d_in[10];
    const float* b3a = (const float*)d_in[11];
    const float* W3b = (const float*)d_in[12];
    const float* b3b = (const float*)d_in[13];
    float* out = (float*)d_out;

    __nv_bfloat16 *hA, *lA, *WTh, *WTl;
    float *y, *h1, *h2;
    cudaGetSymbolAddress((void**)&hA,  g_hA);
    cudaGetSymbolAddress((void**)&lA,  g_lA);
    cudaGetSymbolAddress((void**)&WTh, g_WTh);
    cudaGetSymbolAddress((void**)&WTl, g_WTl);
    cudaGetSymbolAddress((void**)&y,   g_y);
    cudaGetSymbolAddress((void**)&h1,  g_h1);
    cudaGetSymbolAddress((void**)&h2,  g_h2);

    // smem bytes: (2*M + 2*N) * SA * 2
    constexpr int S_L1 = (512 + 64)  * 72  * 2;   // 82944
    constexpr int S_L2 = (512 + 128) * 72  * 2;   // 92160
    constexpr int S_L3 = (512 + 256) * 136 * 2;   // 208896
    cudaFuncSetAttribute(stage2r<64, 32>,   cudaFuncAttributeMaxDynamicSharedMemorySize, S_L1);
    cudaFuncSetAttribute(stage2r<64, 64>,   cudaFuncAttributeMaxDynamicSharedMemorySize, S_L2);
    cudaFuncSetAttribute(stage2r<128, 128>, cudaFuncAttributeMaxDynamicSharedMemorySize, S_L3);

    // ---- layer 1: pos(3) -> 32 ----
    kernelN<3, 32><<<784, 256>>>(pos, W1a, b1a, y);
    kernelE<3, 32, 64><<<2048, 256>>>(y, pos, src, W1a, hA, lA);
    prepT<32, 32, 64><<<16, 256>>>(W1b, WTh, WTl);
    stage2r<64, 32><<<296, 512, S_L1>>>(hA, lA, WTh, WTl, b1b, h1);

    // ---- layer 2: 32 -> 64 ----
    kernelN<32, 64><<<784, 256>>>(h1, W2a, b2a, y);
    kernelE<32, 64, 64><<<2048, 256>>>(y, pos, src, W2a, hA, lA);
    prepT<64, 64, 64><<<16, 256>>>(W2b, WTh, WTl);
    stage2r<64, 64><<<296, 512, S_L2>>>(hA, lA, WTh, WTl, b2b, h2);

    // ---- layer 3: 64 -> 128 ----
    kernelN<64, 128><<<784, 256>>>(h2, W3a, b3a, y);
    kernelE<64, 128, 128><<<2048, 256>>>(y, pos, src, W3a, hA, lA);
    prepT<128, 128, 128><<<64, 256>>>(W3b, WTh, WTl);
    stage2r<128, 128><<<148, 512, S_L3>>>(hA, lA, WTh, WTl, b3b, out);
}

// round 5
// speedup vs baseline: 3.7774x; 1.0982x over previous
#include <cuda_runtime.h>
#include <cuda_bf16.h>
#include <stdint.h>

#define NNODES 100000
#define KNN 6
#define NEDGES 600000

// ---------------- device scratch (no allocation allowed) ----------------
__device__ float g_y [(size_t)NNODES * 128];   // node-level partial (x@Wa_top + ba)
__device__ float g_h1[(size_t)NNODES * 32];
__device__ float g_h2[(size_t)NNODES * 64];

// ---------------- PTX helpers (sm_80+: mma.sync / ldmatrix) ----------------
__device__ __forceinline__ uint32_t s2u(const void* p) {
    uint32_t a;
    asm("{ .reg .u64 t; cvta.to.shared.u64 t, %1; cvt.u32.u64 %0, t; }" : "=r"(a) : "l"(p));
    return a;
}
__device__ __forceinline__ void ldm_x4(uint32_t* r, uint32_t addr) {
    asm volatile("ldmatrix.sync.aligned.m8n8.x4.shared.b16 {%0,%1,%2,%3}, [%4];"
                 : "=r"(r[0]), "=r"(r[1]), "=r"(r[2]), "=r"(r[3]) : "r"(addr));
}
__device__ __forceinline__ void mma_bf16(float* c, const uint32_t* a, const uint32_t* b) {
    asm volatile("mma.sync.aligned.m16n8k16.row.col.f32.bf16.bf16.f32 "
                 "{%0,%1,%2,%3}, {%4,%5,%6,%7}, {%8,%9}, {%0,%1,%2,%3};"
                 : "+f"(c[0]), "+f"(c[1]), "+f"(c[2]), "+f"(c[3])
                 : "r"(a[0]), "r"(a[1]), "r"(a[2]), "r"(a[3]), "r"(b[0]), "r"(b[1]));
}
__device__ __forceinline__ uint32_t pack_bf2(__nv_bfloat16 a, __nv_bfloat16 b) {
    __nv_bfloat162 v = __halves2bfloat162(a, b);
    return *(uint32_t*)&v;
}

// ============ kernelN: y[node] = x @ Wa_top + ba  (warp per node) ============
template<int CIN, int H>
__global__ __launch_bounds__(256) void kernelN(const float* __restrict__ x,
                                               const float* __restrict__ Wa,
                                               const float* __restrict__ ba,
                                               float* __restrict__ y)
{
    constexpr int CPL = H / 32;
    __shared__ float sW[CIN * H];
    __shared__ float sb[H];
    for (int t = threadIdx.x; t < CIN * H; t += 256) sW[t] = Wa[t];
    for (int t = threadIdx.x; t < H;       t += 256) sb[t] = ba[t];
    __syncthreads();

    const int lane = threadIdx.x & 31;
    const int gw = (blockIdx.x * 256 + threadIdx.x) >> 5;
    const int nw = (gridDim.x * 256) >> 5;
    const int c0 = lane * CPL;

    for (int node = gw; node < NNODES; node += nw) {
        float acc[CPL];
        #pragma unroll
        for (int q = 0; q < CPL; q++) acc[q] = sb[c0 + q];
        #pragma unroll 4
        for (int c = 0; c < CIN; c++) {
            float xv = __ldg(&x[(size_t)node * CIN + c]);
            #pragma unroll
            for (int q = 0; q < CPL; q++) acc[q] = fmaf(xv, sW[c * H + c0 + q], acc[q]);
        }
        #pragma unroll
        for (int q = 0; q < CPL; q++) y[(size_t)node * H + c0 + q] = acc[q];
    }
}

// ============ fused stage2F: build A tile in smem from y/pos/src, MMA, 6-row max ===========
// M=256 rows = 252 edges (42 nodes) + 4 dead rows. 512 threads (16 warps); warp w owns
// rows [16w,16w+16). B = Wb^T hi/lo built once per block; A hi/lo built per tile from
// hid[e] = relu(y[src[e]] + dpos @ Wa_pos) split into bf16 hi+lo. z aliases the A region.
// C = Ah*Bh + Ah*Bl + Al*Bh with fp32 accumulators.
template<int H, int N>
__global__ __launch_bounds__(512) void stage2F(const float* __restrict__ y,
                                               const float* __restrict__ pos,
                                               const int*   __restrict__ src,
                                               const float* __restrict__ Wa,   // [(CIN+3)][H]; last 3 rows used
                                               int cin,
                                               const float* __restrict__ Wb,   // [H][N]
                                               const float* __restrict__ bb,
                                               float* __restrict__ out)
{
    constexpr int M    = 256;
    constexpr int SA   = H + 8;            // padded row stride (bf16 elems)
    constexpr int NP   = N + 4;            // padded z row (floats)
    constexpr int NT8  = N / 8;
    constexpr int OFF_AH = 0;
    constexpr int OFF_AL = M * SA * 2;
    constexpr int OFF_BH = 2 * M * SA * 2;
    constexpr int OFF_BL = OFF_BH + N * SA * 2;
    constexpr int OFF_WP = OFF_BL + N * SA * 2;        // 3*H floats
    constexpr int OFF_BB = OFF_WP + 3 * H * 4;         // N floats
    constexpr int OFF_SJ = OFF_BB + N * 4;             // 252 ints
    constexpr int OFF_SD = OFF_SJ + 256 * 4;           // 252*3 floats

    extern __shared__ char smem[];
    const uint32_t sb = s2u(smem);
    float* z   = (float*)smem;                    // aliases A region
    float* sWp = (float*)(smem + OFF_WP);
    float* sbb = (float*)(smem + OFF_BB);
    int*   sj  = (int*)  (smem + OFF_SJ);
    float* sd  = (float*)(smem + OFF_SD);

    const int tid  = threadIdx.x;
    const int wid  = tid >> 5;
    const int lid  = tid & 31;
    const int wrow = wid * 16;

    // ---- block prologue: B tiles (transpose + split), Wa_pos, bias ----
    const float* Wp = Wa + (size_t)cin * H;
    for (int t = tid; t < 3 * H; t += 512) sWp[t] = Wp[t];
    for (int t = tid; t < N;     t += 512) sbb[t] = bb[t];
    for (int t = tid; t < N * H; t += 512) {
        int n = t / H, k = t % H;
        float v = Wb[(size_t)k * N + n];
        __nv_bfloat16 h = __float2bfloat16(v);
        __nv_bfloat16 l = __float2bfloat16(v - __bfloat162float(h));
        *(__nv_bfloat16*)(smem + OFF_BH + (n * SA + k) * 2) = h;
        *(__nv_bfloat16*)(smem + OFF_BL + (n * SA + k) * 2) = l;
    }

    const int lm = lid >> 3, lr = lid & 7;
    const int a_row_off = (lm & 1) * 8 + lr;   // + k-block (lm>>1)*8
    const int b_row_off = (lm >> 1) * 8 + lr;  // + k-block (lm&1)*8
    const int NT = (NEDGES + 251) / 252;

    for (int tile = blockIdx.x; tile < NT; tile += gridDim.x) {
        const int ebase = tile * 252;

        // ---- pass 1: per-edge src index + dpos ----
        if (tid < 252) {
            const int ge = ebase + tid;
            int j = -1;
            float d0 = 0.f, d1 = 0.f, d2 = 0.f;
            if (ge < NEDGES) {
                const int i = ge / KNN;
                j = __ldg(&src[ge]);
                d0 = __ldg(&pos[3 * j + 0]) - __ldg(&pos[3 * i + 0]);
                d1 = __ldg(&pos[3 * j + 1]) - __ldg(&pos[3 * i + 1]);
                d2 = __ldg(&pos[3 * j + 2]) - __ldg(&pos[3 * i + 2]);
            }
            sj[tid] = j;
            sd[tid * 3 + 0] = d0;
            sd[tid * 3 + 1] = d1;
            sd[tid * 3 + 2] = d2;
        }
        __syncthreads();   // sj/sd ready AND prev epilogue done reading z

        // ---- pass 2: build A tile hi/lo in smem ----
        {
            constexpr int PPR = H / 2;   // bf16 pairs per row
            for (int idx = tid; idx < M * PPR; idx += 512) {
                const int r = idx / PPR, c = (idx % PPR) * 2;
                uint32_t hv = 0u, lv = 0u;
                if (r < 252 && sj[r] >= 0) {
                    const int j = sj[r];
                    const float d0 = sd[r * 3], d1 = sd[r * 3 + 1], d2 = sd[r * 3 + 2];
                    const float2 yv = *(const float2*)&y[(size_t)j * H + c];
                    float v0 = yv.x, v1 = yv.y;
                    v0 = fmaf(d0, sWp[c],         v0);
                    v1 = fmaf(d0, sWp[c + 1],     v1);
                    v0 = fmaf(d1, sWp[H + c],     v0);
                    v1 = fmaf(d1, sWp[H + c + 1], v1);
                    v0 = fmaf(d2, sWp[2 * H + c],     v0);
                    v1 = fmaf(d2, sWp[2 * H + c + 1], v1);
                    v0 = fmaxf(v0, 0.f); v1 = fmaxf(v1, 0.f);
                    __nv_bfloat16 h0 = __float2bfloat16(v0);
                    __nv_bfloat16 h1 = __float2bfloat16(v1);
                    __nv_bfloat16 l0 = __float2bfloat16(v0 - __bfloat162float(h0));
                    __nv_bfloat16 l1 = __float2bfloat16(v1 - __bfloat162float(h1));
                    hv = pack_bf2(h0, h1);
                    lv = pack_bf2(l0, l1);
                }
                *(uint32_t*)(smem + OFF_AH + (r * SA + c) * 2) = hv;
                *(uint32_t*)(smem + OFF_AL + (r * SA + c) * 2) = lv;
            }
        }
        __syncthreads();

        // ---- MMA mainloop ----
        float c[NT8][4];
        #pragma unroll
        for (int t = 0; t < NT8; t++)
            #pragma unroll
            for (int q = 0; q < 4; q++) c[t][q] = 0.f;

        #pragma unroll
        for (int k0 = 0; k0 < H; k0 += 16) {
            uint32_t ah[4], al[4];
            const uint32_t a_off = ((wrow + a_row_off) * SA + k0 + (lm >> 1) * 8) * 2;
            ldm_x4(ah, sb + OFF_AH + a_off);
            ldm_x4(al, sb + OFF_AL + a_off);

            #pragma unroll
            for (int np = 0; np < NT8 / 2; np++) {
                uint32_t bh[4], bl[4];
                const uint32_t b_off = ((np * 16 + b_row_off) * SA + k0 + (lm & 1) * 8) * 2;
                ldm_x4(bh, sb + OFF_BH + b_off);
                ldm_x4(bl, sb + OFF_BL + b_off);
                mma_bf16(c[2 * np],     ah, &bh[0]);
                mma_bf16(c[2 * np],     ah, &bl[0]);
                mma_bf16(c[2 * np],     al, &bh[0]);
                mma_bf16(c[2 * np + 1], ah, &bh[2]);
                mma_bf16(c[2 * np + 1], ah, &bl[2]);
                mma_bf16(c[2 * np + 1], al, &bh[2]);
            }
        }
        __syncthreads();   // all warps done reading A before z overwrites it

        // ---- store C frags to z ----
        {
            const int qr = lid >> 2, qc = (lid & 3) * 2;
            #pragma unroll
            for (int t = 0; t < NT8; t++) {
                float* zp = z + (wrow + qr) * NP + t * 8 + qc;
                zp[0] = c[t][0];
                zp[1] = c[t][1];
                zp[8 * NP]     = c[t][2];
                zp[8 * NP + 1] = c[t][3];
            }
        }
        __syncthreads();

        // ---- 6-row max + bias + relu -> out (42 nodes per tile) ----
        for (int t = tid; t < 42 * N; t += 512) {
            const int g = t / N, col = t % N;
            const int node = tile * 42 + g;
            if (node < NNODES) {
                const float* zp = z + (6 * g) * NP + col;
                float m = zp[0];
                m = fmaxf(m, zp[NP]);
                m = fmaxf(m, zp[2 * NP]);
                m = fmaxf(m, zp[3 * NP]);
                m = fmaxf(m, zp[4 * NP]);
                m = fmaxf(m, zp[5 * NP]);
                out[(size_t)node * N + col] = fmaxf(m + sbb[col], 0.f);
            }
        }
    }
}

template<int H, int N>
static constexpr int smemF() {
    constexpr int SA = H + 8;
    return 2 * 256 * SA * 2      // A hi/lo
         + 2 * N * SA * 2        // B hi/lo
         + 3 * H * 4             // Wa_pos
         + N * 4                 // bias
         + 256 * 4               // sj
         + 252 * 3 * 4 + 64;     // sd + slack
}

// ---------------- host ----------------
extern "C" void kernel_launch(void* const* d_in, const int* in_sizes, int n_in,
                              void* d_out, int out_size)
{
    const float* pos = (const float*)d_in[0];
    const int*   src = (const int*)d_in[1];   // row 0 of edge_index
    const float* W1a = (const float*)d_in[2];
    const float* b1a = (const float*)d_in[3];
    const float* W1b = (const float*)d_in[4];
    const float* b1b = (const float*)d_in[5];
    const float* W2a = (const float*)d_in[6];
    const float* b2a = (const float*)d_in[7];
    const float* W2b = (const float*)d_in[8];
    const float* b2b = (const float*)d_in[9];
    const float* W3a = (const float*)d_in[10];
    const float* b3a = (const float*)d_in[11];
    const float* W3b = (const float*)d_in[12];
    const float* b3b = (const float*)d_in[13];
    float* out = (float*)d_out;

    float *y, *h1, *h2;
    cudaGetSymbolAddress((void**)&y,  g_y);
    cudaGetSymbolAddress((void**)&h1, g_h1);
    cudaGetSymbolAddress((void**)&h2, g_h2);

    constexpr int S1 = smemF<32, 32>();     // ~47 KB
    constexpr int S2 = smemF<64, 64>();     // ~94 KB
    constexpr int S3 = smemF<128, 128>();   // ~214 KB
    cudaFuncSetAttribute(stage2F<32, 32>,   cudaFuncAttributeMaxDynamicSharedMemorySize, S1);
    cudaFuncSetAttribute(stage2F<64, 64>,   cudaFuncAttributeMaxDynamicSharedMemorySize, S2);
    cudaFuncSetAttribute(stage2F<128, 128>, cudaFuncAttributeMaxDynamicSharedMemorySize, S3);

    // ---- layer 1: pos(3) -> 32 ----
    kernelN<3, 32><<<784, 256>>>(pos, W1a, b1a, y);
    stage2F<32, 32><<<296, 512, S1>>>(y, pos, src, W1a, 3, W1b, b1b, h1);

    // ---- layer 2: 32 -> 64 ----
    kernelN<32, 64><<<784, 256>>>(h1, W2a, b2a, y);
    stage2F<64, 64><<<296, 512, S2>>>(y, pos, src, W2a, 32, W2b, b2b, h2);

    // ---- layer 3: 64 -> 128 ----
    kernelN<64, 128><<<784, 256>>>(h2, W3a, b3a, y);
    stage2F<128, 128><<<148, 512, S3>>>(y, pos, src, W3a, 64, W3b, b3b, out);
}